// round 13
// baseline (speedup 1.0000x reference)
#include <cuda_runtime.h>
#include <cuda_bf16.h>
#include <math.h>
#include <stdint.h>

// Problem constants
#define BB   64
#define SS   512
#define DD   1024
#define HH   512
#define TT   25
#define MROWS (BB*SS)          // 32768

// -------- scratch (allocation-free: __device__ globals) --------
__device__ uint4 g_Xs[(size_t)MROWS * DD / 8];   // 64 MB bf16 X, tiled+swizzled
__device__ uint4 g_W1s[(size_t)DD * HH / 8];     // 1 MB bf16 W1, tiled+swizzled
__device__ float g_Ep[4][(size_t)MROWS * TT];    // split-K emission partials
__device__ float g_E[(size_t)MROWS * TT + 32];   // emissions (+pad)
__device__ float g_expE[(size_t)MROWS * TT + 32];// exp(emissions) (+pad)
__device__ float g_ll[BB];                       // per-batch log-likelihood

// ============================================================================
// convert_all: X -> bf16 tiles (blocks 0..16383), W1 -> bf16 tiles (the rest)
// ============================================================================
#define XBLOCKS ((MROWS * DD / 8) / 256)   // 16384
#define WBLOCKS ((DD * HH / 8) / 256)      // 256

__global__ __launch_bounds__(256)
void convert_all_kernel(const float* __restrict__ X,
                        const float* __restrict__ W1)
{
    if (blockIdx.x < XBLOCKS) {
        int id = blockIdx.x * 256 + threadIdx.x;
        int tile   = id >> 9;
        int within = id & 511;
        int r  = within >> 2;
        int cp = within & 3;
        int mtile = tile >> 5;
        int ktile = tile & 31;
        int sw = (r & 3) ^ ((r >> 2) & 1);
        int c  = cp ^ sw;
        int m = mtile * 128 + r;
        int k = ktile * 32 + c * 8;
        const float4* src = (const float4*)(X + (size_t)m * DD + k);
        float4 x0 = src[0], x1 = src[1];
        __nv_bfloat162 p0 = __floats2bfloat162_rn(x0.x, x0.y);
        __nv_bfloat162 p1 = __floats2bfloat162_rn(x0.z, x0.w);
        __nv_bfloat162 p2 = __floats2bfloat162_rn(x1.x, x1.y);
        __nv_bfloat162 p3 = __floats2bfloat162_rn(x1.z, x1.w);
        uint4 out;
        out.x = *(uint32_t*)&p0; out.y = *(uint32_t*)&p1;
        out.z = *(uint32_t*)&p2; out.w = *(uint32_t*)&p3;
        g_Xs[id] = out;
    } else {
        int id = (blockIdx.x - XBLOCKS) * 256 + threadIdx.x;
        int tile   = id >> 9;
        int within = id & 511;
        int k  = within >> 4;
        int cp = within & 15;
        int ktile = tile >> 2;
        int ntile = tile & 3;
        int c = cp ^ (k & 7);
        int krow = ktile * 32 + k;
        int n = ntile * 128 + c * 8;
        const float4* src = (const float4*)(W1 + (size_t)krow * HH + n);
        float4 x0 = src[0], x1 = src[1];
        __nv_bfloat162 p0 = __floats2bfloat162_rn(x0.x, x0.y);
        __nv_bfloat162 p1 = __floats2bfloat162_rn(x0.z, x0.w);
        __nv_bfloat162 p2 = __floats2bfloat162_rn(x1.x, x1.y);
        __nv_bfloat162 p3 = __floats2bfloat162_rn(x1.z, x1.w);
        uint4 out;
        out.x = *(uint32_t*)&p0; out.y = *(uint32_t*)&p1;
        out.z = *(uint32_t*)&p2; out.w = *(uint32_t*)&p3;
        g_W1s[id] = out;
    }
}

// ============================================================================
// GEMM1 (tensor cores): H = gelu(X @ W1 + b1), fused GEMM2 partials
// ============================================================================
#define NIT (DD / 32)   // 32 k-iterations
#define STG 16384       // per stage: 8KB A + 8KB B
#define SMEM_DYN (4 * STG)
#define W2_OFF  49152

__device__ __forceinline__ void cp_async16(uint32_t saddr, const void* gaddr) {
    asm volatile("cp.async.cg.shared.global [%0], [%1], 16;\n"
                 :: "r"(saddr), "l"(gaddr));
}
__device__ __forceinline__ void cp_commit() {
    asm volatile("cp.async.commit_group;\n");
}
__device__ __forceinline__ void ldmatrix_x4(uint32_t* r, uint32_t addr) {
    asm volatile("ldmatrix.sync.aligned.m8n8.x4.shared.b16 {%0,%1,%2,%3}, [%4];"
                 : "=r"(r[0]), "=r"(r[1]), "=r"(r[2]), "=r"(r[3]) : "r"(addr));
}
__device__ __forceinline__ void ldmatrix_x4_trans(uint32_t* r, uint32_t addr) {
    asm volatile("ldmatrix.sync.aligned.m8n8.x4.trans.shared.b16 {%0,%1,%2,%3}, [%4];"
                 : "=r"(r[0]), "=r"(r[1]), "=r"(r[2]), "=r"(r[3]) : "r"(addr));
}
__device__ __forceinline__ void mma_bf16(float* c, const uint32_t* a,
                                         uint32_t b0, uint32_t b1) {
    asm volatile("mma.sync.aligned.m16n8k16.row.col.f32.bf16.bf16.f32 "
                 "{%0,%1,%2,%3},{%4,%5,%6,%7},{%8,%9},{%0,%1,%2,%3};"
                 : "+f"(c[0]), "+f"(c[1]), "+f"(c[2]), "+f"(c[3])
                 : "r"(a[0]), "r"(a[1]), "r"(a[2]), "r"(a[3]), "r"(b0), "r"(b1));
}

__global__ __launch_bounds__(256)
void gemm1_fused_kernel(const float* __restrict__ b1,
                        const float* __restrict__ W2)
{
    extern __shared__ __align__(16) unsigned char sm[];

    const int tid  = threadIdx.x;
    const int lane = tid & 31;
    const int w    = tid >> 5;
    const int wm   = w & 3;
    const int wn   = w >> 2;
    const int ntile = blockIdx.x;   // 0..3
    const int mtile = blockIdx.y;   // 0..255

    uint32_t sbase = (uint32_t)__cvta_generic_to_shared(&sm[0]);

    auto issue = [&](int stage, int it) {
        uint32_t sa = sbase + stage * STG;
        uint32_t sb = sa + 8192;
        const uint4* gA = g_Xs + ((size_t)(mtile * 32 + it)) * 512;
        const uint4* gB = g_W1s + ((size_t)(it * 4 + ntile)) * 512;
        cp_async16(sa + tid * 16,         gA + tid);
        cp_async16(sa + (tid + 256) * 16, gA + tid + 256);
        cp_async16(sb + tid * 16,         gB + tid);
        cp_async16(sb + (tid + 256) * 16, gB + tid + 256);
    };

    int rA0 = wm * 32 + (lane & 15);
    int rA1 = rA0 + 16;
    int swzA0 = (rA0 & 3) ^ ((rA0 >> 2) & 1);
    int swzA1 = (rA1 & 3) ^ ((rA1 >> 2) & 1);
    int caBase = lane >> 4;
    int kBoff = lane & 15;
    int cbBase = wn * 8 + (lane >> 4);
    int kx = lane & 7;

    float c[2][8][4];
    #pragma unroll
    for (int im = 0; im < 2; im++)
        #pragma unroll
        for (int in = 0; in < 8; in++)
            #pragma unroll
            for (int r = 0; r < 4; r++) c[im][in][r] = 0.f;

    issue(0, 0); cp_commit();
    issue(1, 1); cp_commit();
    issue(2, 2); cp_commit();

    for (int it = 0; it < NIT; ++it) {
        if (it <= NIT - 3)      asm volatile("cp.async.wait_group 2;\n");
        else if (it == NIT - 2) asm volatile("cp.async.wait_group 1;\n");
        else                    asm volatile("cp.async.wait_group 0;\n");
        __syncthreads();

        if (it + 3 < NIT) {
            issue((it + 3) & 3, it + 3);
            cp_commit();
        }

        const int st = it & 3;
        uint32_t abase = sbase + st * STG;
        uint32_t bbase = abase + 8192;

        #pragma unroll
        for (int s = 0; s < 2; s++) {
            uint32_t a[2][4];
            {
                int ch0 = (2 * s + caBase) ^ swzA0;
                int ch1 = (2 * s + caBase) ^ swzA1;
                ldmatrix_x4(a[0], abase + rA0 * 64 + ch0 * 16);
                ldmatrix_x4(a[1], abase + rA1 * 64 + ch1 * 16);
            }
            uint32_t bt[4][4];
            #pragma unroll
            for (int inb = 0; inb < 4; inb++) {
                int ch = (cbBase + inb * 2) ^ kx;
                ldmatrix_x4_trans(bt[inb], bbase + (16 * s + kBoff) * 256 + ch * 16);
            }
            #pragma unroll
            for (int im = 0; im < 2; im++)
                #pragma unroll
                for (int in = 0; in < 8; in++) {
                    uint32_t b0 = bt[in >> 1][(in & 1) * 2];
                    uint32_t b1r = bt[in >> 1][(in & 1) * 2 + 1];
                    mma_bf16(c[im][in], a[im], b0, b1r);
                }
        }
    }
    __syncthreads();

    // ======================= fused epilogue =======================
    const int g  = lane >> 2;
    const int tg = lane & 3;
    const uint32_t hbase = sbase;
    const uint32_t w2b   = sbase + W2_OFF;
    {
        const int nbase = ntile * 128 + wn * 64;
        #pragma unroll
        for (int im = 0; im < 2; im++) {
            #pragma unroll
            for (int in = 0; in < 8; in++) {
                int col = nbase + in * 8 + tg * 2;
                float bias0 = __ldg(&b1[col]);
                float bias1 = __ldg(&b1[col + 1]);
                #pragma unroll
                for (int h = 0; h < 2; h++) {
                    int row = wm * 32 + im * 16 + g + 8 * h;
                    float v0 = c[im][in][2 * h]     + bias0;
                    float v1 = c[im][in][2 * h + 1] + bias1;
                    v0 = 0.5f * v0 * (1.0f + erff(v0 * 0.70710678118654752f));
                    v1 = 0.5f * v1 * (1.0f + erff(v1 * 0.70710678118654752f));
                    __nv_bfloat162 p = __floats2bfloat162_rn(v0, v1);
                    int physu = ((in ^ (row & 7)) + 8 * wn) * 4 + tg;
                    uint32_t addr = hbase + row * 256 + physu * 4;
                    asm volatile("st.shared.b32 [%0], %1;\n"
                                 :: "r"(addr), "r"(*(uint32_t*)&p));
                }
            }
        }
    }
    for (int idx = tid; idx < 128 * 32; idx += 256) {
        int r  = idx >> 5;
        int cc = idx & 31;
        float v = (cc < TT) ? __ldg(&W2[(size_t)(ntile * 128 + r) * TT + cc]) : 0.f;
        __nv_bfloat16 bv = __float2bfloat16(v);
        uint32_t addr = w2b + r * 80 + cc * 2;
        asm volatile("st.shared.b16 [%0], %1;\n"
                     :: "r"(addr), "h"(*(uint16_t*)&bv));
    }
    __syncthreads();

    {
        float e[4][4];
        #pragma unroll
        for (int j = 0; j < 4; j++)
            #pragma unroll
            for (int r = 0; r < 4; r++) e[j][r] = 0.f;

        const int arow = w * 16 + (lane & 15);
        const int asw  = arow & 7;

        #pragma unroll
        for (int k0 = 0; k0 < 128; k0 += 16) {
            uint32_t a[4];
            int ch = ((k0 >> 3) + (lane >> 4)) ^ asw;
            ldmatrix_x4(a, hbase + arow * 256 + ch * 16);
            #pragma unroll
            for (int nt2 = 0; nt2 < 2; nt2++) {
                uint32_t bt[4];
                uint32_t baddr = w2b + (k0 + (lane & 15)) * 80
                               + ((lane >> 4) + 2 * nt2) * 16;
                ldmatrix_x4_trans(bt, baddr);
                mma_bf16(e[nt2 * 2 + 0], a, bt[0], bt[1]);
                mma_bf16(e[nt2 * 2 + 1], a, bt[2], bt[3]);
            }
        }

        float* Ep = g_Ep[ntile];
        #pragma unroll
        for (int j = 0; j < 4; j++) {
            int col = j * 8 + tg * 2;
            #pragma unroll
            for (int h2 = 0; h2 < 2; h2++) {
                int row = mtile * 128 + w * 16 + g + 8 * h2;
                if (col < TT)     Ep[(size_t)row * TT + col]     = e[j][2 * h2];
                if (col + 1 < TT) Ep[(size_t)row * TT + col + 1] = e[j][2 * h2 + 1];
            }
        }
    }
}

// ============================================================================
// reduce: E = sum_k Ep[k] + b2 ; also expE = exp(E)
// ============================================================================
__global__ __launch_bounds__(256)
void reduce_E_kernel(const float* __restrict__ b2)
{
    int i = blockIdx.x * 256 + threadIdx.x;
    if (i < MROWS * TT) {
        float s = g_Ep[0][i] + g_Ep[1][i] + g_Ep[2][i] + g_Ep[3][i];
        float e = s + __ldg(&b2[i % TT]);
        g_E[i] = e;
        g_expE[i] = __expf(e);
    }
}

// ============================================================================
// CRF: linear-domain fwd/bwd scans with the 25 transition weights held in
// 25 NAMED scalar registers (not indexable -> cannot spill to local memory).
// __launch_bounds__(64) lifts the register cap.
// ============================================================================
#define FOREACH_W(F) \
    F(0)  F(1)  F(2)  F(3)  F(4)  F(5)  F(6)  F(7)  F(8)  F(9)  \
    F(10) F(11) F(12) F(13) F(14) F(15) F(16) F(17) F(18) F(19) \
    F(20) F(21) F(22) F(23) F(24)

#define DECL_W(i)  float w##i;
#define LOAD_W(i)  w##i = __expf(trans_sh[wrow ? (rc * TT + i) : (i * TT + rc)]);

// 25-term matvec: out = sum_i shfl(src, i) * w_i   (4 accumulator trees)
#define MATVEC25(src, out) do {                                   \
    float _a0, _a1, _a2, _a3;                                     \
    _a0 = __shfl_sync(full, (src), 0)  * w0;                      \
    _a1 = __shfl_sync(full, (src), 1)  * w1;                      \
    _a2 = __shfl_sync(full, (src), 2)  * w2;                      \
    _a3 = __shfl_sync(full, (src), 3)  * w3;                      \
    _a0 = fmaf(__shfl_sync(full, (src), 4),  w4,  _a0);           \
    _a1 = fmaf(__shfl_sync(full, (src), 5),  w5,  _a1);           \
    _a2 = fmaf(__shfl_sync(full, (src), 6),  w6,  _a2);           \
    _a3 = fmaf(__shfl_sync(full, (src), 7),  w7,  _a3);           \
    _a0 = fmaf(__shfl_sync(full, (src), 8),  w8,  _a0);           \
    _a1 = fmaf(__shfl_sync(full, (src), 9),  w9,  _a1);           \
    _a2 = fmaf(__shfl_sync(full, (src), 10), w10, _a2);           \
    _a3 = fmaf(__shfl_sync(full, (src), 11), w11, _a3);           \
    _a0 = fmaf(__shfl_sync(full, (src), 12), w12, _a0);           \
    _a1 = fmaf(__shfl_sync(full, (src), 13), w13, _a1);           \
    _a2 = fmaf(__shfl_sync(full, (src), 14), w14, _a2);           \
    _a3 = fmaf(__shfl_sync(full, (src), 15), w15, _a3);           \
    _a0 = fmaf(__shfl_sync(full, (src), 16), w16, _a0);           \
    _a1 = fmaf(__shfl_sync(full, (src), 17), w17, _a1);           \
    _a2 = fmaf(__shfl_sync(full, (src), 18), w18, _a2);           \
    _a3 = fmaf(__shfl_sync(full, (src), 19), w19, _a3);           \
    _a0 = fmaf(__shfl_sync(full, (src), 20), w20, _a0);           \
    _a1 = fmaf(__shfl_sync(full, (src), 21), w21, _a1);           \
    _a2 = fmaf(__shfl_sync(full, (src), 22), w22, _a2);           \
    _a3 = fmaf(__shfl_sync(full, (src), 23), w23, _a3);           \
    _a0 = fmaf(__shfl_sync(full, (src), 24), w24, _a0);           \
    (out) = (_a0 + _a1) + (_a2 + _a3);                            \
} while (0)

__global__ __launch_bounds__(64)
void crf_kernel(const float* __restrict__ start_t,
                const float* __restrict__ end_t,
                const float* __restrict__ trans,
                const void*  __restrict__ labels_raw,
                const void*  __restrict__ mask_raw)
{
    __shared__ float trans_sh[TT * TT];
    __shared__ unsigned char msh[SS];
    __shared__ float comb[64];
    __shared__ float nacc[2];
    __shared__ int   ncnt[2];

    const int b = blockIdx.x;
    const int tid = threadIdx.x;      // 0..63
    const int lane = tid & 31;
    const int warp = tid >> 5;
    const unsigned full = 0xffffffffu;

    for (int i = tid; i < TT * TT; i += 64) trans_sh[i] = trans[i];

    // ---- label dtype detect ----
    const int* li = (const int*)labels_raw;
    unsigned ball = __ballot_sync(full, li[2 * lane + 1] == 0);
    const int lstride = (ball == full) ? 2 : 1;

    // ---- mask encoding detect ----
    const unsigned* mw = (const unsigned*)mask_raw;
    unsigned any_high = 0, any_float = 0;
    for (int i = lane; i < 256; i += 32) {
        unsigned wv = mw[i];
        any_float |= (wv == 0x3F800000u);
        any_high  |= (wv & 0xFFFFFF00u) && (wv != 0x3F800000u);
    }
    const bool is_float = __ballot_sync(full, any_float != 0) != 0;
    const bool is_byte  = !is_float && (__ballot_sync(full, any_high != 0) != 0);

    const int base = b * SS;

    int myok = 1;
    for (int t = tid; t < SS; t += 64) {
        unsigned char mv;
        if (is_float)      mv = (((const float*)mask_raw)[base + t] != 0.f);
        else if (is_byte)  mv = (((const unsigned char*)mask_raw)[base + t] != 0);
        else               mv = (((const int*)mask_raw)[base + t] != 0);
        msh[t] = mv;
        myok &= mv;
    }
    const int allones = __syncthreads_and(myok);

    const float* Eb  = g_E    + (size_t)base * TT;
    const float* Xb  = g_expE + (size_t)base * TT;

    // ---- numerator partials (both warps, 64-strided) ----
    float acc = 0.f;
    int cnt = 0;
    for (int t = tid; t < SS; t += 64) cnt += msh[t];
    for (int t = 1 + tid; t < SS; t += 64) {
        if (msh[t]) {
            int lt = li[(base + t) * lstride];
            int lp = li[(base + t - 1) * lstride];
            acc += trans_sh[lp * TT + lt] + Eb[t * TT + lt];
        }
    }
    #pragma unroll
    for (int off = 16; off > 0; off >>= 1) {
        acc += __shfl_xor_sync(full, acc, off);
        cnt += __shfl_xor_sync(full, cnt, off);
    }
    if (lane == 0) { nacc[warp] = acc; ncnt[warp] = cnt; }

    // ---- 25 named weight registers: exp(trans) col (fwd) / row (bwd) ----
    const int rc = (lane < TT) ? lane : (TT - 1);
    const int wrow = warp;          // warp0: column of trans; warp1: row
    FOREACH_W(DECL_W)
    FOREACH_W(LOAD_W)

    if (allones) {
        if (warp == 0) {
            // forward, linear domain: A_t = expE_t * (W^T A_{t-1})
            float p = (lane < TT) ? __expf(start_t[lane] + Eb[lane]) : 0.f;
            float logS = 0.f;
            float e_next = (lane < TT) ? Xb[1 * TT + lane] : 0.f;
            for (int t = 1; t <= 256; t++) {
                float e_cur = e_next;
                if (t < 256) e_next = (lane < TT) ? Xb[(t + 1) * TT + lane] : 0.f;
                float s;
                MATVEC25(p, s);
                p = s * e_cur;
                if ((t & 15) == 0) {
                    float cc = __shfl_sync(full, p, 0);
                    p *= (1.0f / cc);
                    logS += __logf(cc);
                }
            }
            comb[lane] = (lane < TT) ? (__logf(p) + logS) : -INFINITY;
        } else {
            // backward, linear domain: B_{t-1} = W (expE_t ⊙ B_t)
            float p = (lane < TT) ? __expf(end_t[lane]) : 0.f;
            float logS = 0.f;
            float e_next = (lane < TT) ? Xb[511 * TT + lane] : 0.f;
            for (int t = 511; t >= 257; t--) {
                float e_cur = e_next;
                if (t > 257) e_next = (lane < TT) ? Xb[(t - 1) * TT + lane] : 0.f;
                float q = p * e_cur;
                float s;
                MATVEC25(q, s);
                p = s;
                if ((t & 15) == 0) {
                    float cc = __shfl_sync(full, p, 0);
                    p *= (1.0f / cc);
                    logS += __logf(cc);
                }
            }
            comb[32 + lane] = (lane < TT) ? (__logf(p) + logS) : -INFINITY;
        }
        __syncthreads();

        if (warp == 0) {
            float v = (lane < TT) ? (comb[lane] + comb[32 + lane]) : -INFINITY;
            float M2 = v;
            #pragma unroll
            for (int off = 16; off > 0; off >>= 1)
                M2 = fmaxf(M2, __shfl_xor_sync(full, M2, off));
            float s2 = (lane < TT) ? __expf(v - M2) : 0.f;
            #pragma unroll
            for (int off = 16; off > 0; off >>= 1)
                s2 += __shfl_xor_sync(full, s2, off);

            if (lane == 0) {
                int lab0 = li[base * lstride];
                float score0 = start_t[lab0] + Eb[lab0];
                int last_tag = li[(base + SS - 1) * lstride];
                float numerator = score0 + (nacc[0] + nacc[1]) + end_t[last_tag];
                float logZ = M2 + __logf(s2);
                g_ll[b] = numerator - logZ;
            }
        }
    } else {
        // -------- fallback: serial masked log-domain scan in warp 0 --------
        __syncthreads();
        if (warp == 0) {
            float alpha = (lane < TT) ? (start_t[lane] + Eb[lane]) : -INFINITY;
            float e_next = (lane < TT) ? Eb[1 * TT + lane] : 0.f;
            unsigned char m_next = msh[1];
            for (int t = 1; t < SS; t++) {
                float e_cur = e_next;
                unsigned char m_cur = m_next;
                if (t + 1 < SS) {
                    e_next = (lane < TT) ? Eb[(t + 1) * TT + lane] : 0.f;
                    m_next = msh[t + 1];
                }
                float M = __shfl_sync(full, alpha, 0);
                float p = __expf(alpha - M);
                float s;
                MATVEC25(p, s);
                float nv = e_cur + M + __logf(s);
                if (lane < TT && m_cur) alpha = nv;
            }
            float v = (lane < TT) ? (alpha + end_t[lane]) : -INFINITY;
            float M2 = v;
            #pragma unroll
            for (int off = 16; off > 0; off >>= 1)
                M2 = fmaxf(M2, __shfl_xor_sync(full, M2, off));
            float s2 = (lane < TT) ? __expf(v - M2) : 0.f;
            #pragma unroll
            for (int off = 16; off > 0; off >>= 1)
                s2 += __shfl_xor_sync(full, s2, off);

            if (lane == 0) {
                int lab0 = li[base * lstride];
                float score0 = start_t[lab0] + Eb[lab0];
                int last_idx = (ncnt[0] + ncnt[1]) - 1;
                int last_tag = li[(base + last_idx) * lstride];
                float numerator = score0 + (nacc[0] + nacc[1]) + end_t[last_tag];
                float logZ = M2 + __logf(s2);
                g_ll[b] = numerator - logZ;
            }
        }
    }
}

// ============================================================================
// finalize: out = -mean(ll)
// ============================================================================
__global__ void finalize_kernel(float* __restrict__ out)
{
    __shared__ float sbuf[2];
    const int l = threadIdx.x; // 64 threads
    float v = g_ll[l];
    #pragma unroll
    for (int off = 16; off > 0; off >>= 1)
        v += __shfl_xor_sync(0xffffffffu, v, off);
    if ((l & 31) == 0) sbuf[l >> 5] = v;
    __syncthreads();
    if (l == 0) out[0] = -(sbuf[0] + sbuf[1]) / (float)BB;
}

// ============================================================================
// launch  (crf at index 3 -> profiled)
// ============================================================================
extern "C" void kernel_launch(void* const* d_in, const int* in_sizes, int n_in,
                              void* d_out, int out_size)
{
    const float* X       = (const float*)d_in[0];
    const float* W1      = (const float*)d_in[1];
    const float* b1      = (const float*)d_in[2];
    const float* W2      = (const float*)d_in[3];
    const float* b2      = (const float*)d_in[4];
    const float* start_t = (const float*)d_in[5];
    const float* end_t   = (const float*)d_in[6];
    const float* trans   = (const float*)d_in[7];
    const void*  labels  = d_in[8];
    const void*  mask    = d_in[9];
    float* out = (float*)d_out;

    convert_all_kernel<<<XBLOCKS + WBLOCKS, 256>>>(X, W1);

    cudaFuncSetAttribute(gemm1_fused_kernel,
                         cudaFuncAttributeMaxDynamicSharedMemorySize, SMEM_DYN);
    dim3 g1(HH / 128, MROWS / 128);
    gemm1_fused_kernel<<<g1, 256, SMEM_DYN>>>(b1, W2);

    reduce_E_kernel<<<(MROWS * TT + 255) / 256, 256>>>(b2);

    crf_kernel<<<BB, 64>>>(start_t, end_t, trans, labels, mask);

    finalize_kernel<<<1, 64>>>(out);
}

// round 14
// speedup vs baseline: 1.0196x; 1.0196x over previous
#include <cuda_runtime.h>
#include <cuda_bf16.h>
#include <math.h>
#include <stdint.h>

// Problem constants
#define BB   64
#define SS   512
#define DD   1024
#define HH   512
#define TT   25
#define MROWS (BB*SS)          // 32768

// -------- scratch (allocation-free: __device__ globals) --------
__device__ uint4 g_Xs[(size_t)MROWS * DD / 8];   // 64 MB bf16 X, tiled+swizzled
__device__ uint4 g_W1s[(size_t)DD * HH / 8];     // 1 MB bf16 W1, tiled+swizzled
__device__ float g_Ep[4][(size_t)MROWS * TT];    // split-K emission partials
__device__ float g_E[(size_t)MROWS * TT + 32];   // emissions (+pad)
__device__ float g_expE[(size_t)MROWS * TT + 32];// exp(emissions) (+pad)
__device__ float g_ll[BB];                       // per-batch log-likelihood

// ============================================================================
// convert_all: X -> bf16 tiles (blocks 0..16383), W1 -> bf16 tiles (the rest)
// ============================================================================
#define XBLOCKS ((MROWS * DD / 8) / 256)   // 16384
#define WBLOCKS ((DD * HH / 8) / 256)      // 256

__global__ __launch_bounds__(256)
void convert_all_kernel(const float* __restrict__ X,
                        const float* __restrict__ W1)
{
    if (blockIdx.x < XBLOCKS) {
        int id = blockIdx.x * 256 + threadIdx.x;
        int tile   = id >> 9;
        int within = id & 511;
        int r  = within >> 2;
        int cp = within & 3;
        int mtile = tile >> 5;
        int ktile = tile & 31;
        int sw = (r & 3) ^ ((r >> 2) & 1);
        int c  = cp ^ sw;
        int m = mtile * 128 + r;
        int k = ktile * 32 + c * 8;
        const float4* src = (const float4*)(X + (size_t)m * DD + k);
        float4 x0 = src[0], x1 = src[1];
        __nv_bfloat162 p0 = __floats2bfloat162_rn(x0.x, x0.y);
        __nv_bfloat162 p1 = __floats2bfloat162_rn(x0.z, x0.w);
        __nv_bfloat162 p2 = __floats2bfloat162_rn(x1.x, x1.y);
        __nv_bfloat162 p3 = __floats2bfloat162_rn(x1.z, x1.w);
        uint4 out;
        out.x = *(uint32_t*)&p0; out.y = *(uint32_t*)&p1;
        out.z = *(uint32_t*)&p2; out.w = *(uint32_t*)&p3;
        g_Xs[id] = out;
    } else {
        int id = (blockIdx.x - XBLOCKS) * 256 + threadIdx.x;
        int tile   = id >> 9;
        int within = id & 511;
        int k  = within >> 4;
        int cp = within & 15;
        int ktile = tile >> 2;
        int ntile = tile & 3;
        int c = cp ^ (k & 7);
        int krow = ktile * 32 + k;
        int n = ntile * 128 + c * 8;
        const float4* src = (const float4*)(W1 + (size_t)krow * HH + n);
        float4 x0 = src[0], x1 = src[1];
        __nv_bfloat162 p0 = __floats2bfloat162_rn(x0.x, x0.y);
        __nv_bfloat162 p1 = __floats2bfloat162_rn(x0.z, x0.w);
        __nv_bfloat162 p2 = __floats2bfloat162_rn(x1.x, x1.y);
        __nv_bfloat162 p3 = __floats2bfloat162_rn(x1.z, x1.w);
        uint4 out;
        out.x = *(uint32_t*)&p0; out.y = *(uint32_t*)&p1;
        out.z = *(uint32_t*)&p2; out.w = *(uint32_t*)&p3;
        g_W1s[id] = out;
    }
}

// ============================================================================
// GEMM1 (tensor cores): H = gelu(X @ W1 + b1), fused GEMM2 partials
// ============================================================================
#define NIT (DD / 32)   // 32 k-iterations
#define STG 16384       // per stage: 8KB A + 8KB B
#define SMEM_DYN (4 * STG)
#define W2_OFF  49152

__device__ __forceinline__ void cp_async16(uint32_t saddr, const void* gaddr) {
    asm volatile("cp.async.cg.shared.global [%0], [%1], 16;\n"
                 :: "r"(saddr), "l"(gaddr));
}
__device__ __forceinline__ void cp_commit() {
    asm volatile("cp.async.commit_group;\n");
}
__device__ __forceinline__ void ldmatrix_x4(uint32_t* r, uint32_t addr) {
    asm volatile("ldmatrix.sync.aligned.m8n8.x4.shared.b16 {%0,%1,%2,%3}, [%4];"
                 : "=r"(r[0]), "=r"(r[1]), "=r"(r[2]), "=r"(r[3]) : "r"(addr));
}
__device__ __forceinline__ void ldmatrix_x4_trans(uint32_t* r, uint32_t addr) {
    asm volatile("ldmatrix.sync.aligned.m8n8.x4.trans.shared.b16 {%0,%1,%2,%3}, [%4];"
                 : "=r"(r[0]), "=r"(r[1]), "=r"(r[2]), "=r"(r[3]) : "r"(addr));
}
__device__ __forceinline__ void mma_bf16(float* c, const uint32_t* a,
                                         uint32_t b0, uint32_t b1) {
    asm volatile("mma.sync.aligned.m16n8k16.row.col.f32.bf16.bf16.f32 "
                 "{%0,%1,%2,%3},{%4,%5,%6,%7},{%8,%9},{%0,%1,%2,%3};"
                 : "+f"(c[0]), "+f"(c[1]), "+f"(c[2]), "+f"(c[3])
                 : "r"(a[0]), "r"(a[1]), "r"(a[2]), "r"(a[3]), "r"(b0), "r"(b1));
}

__global__ __launch_bounds__(256)
void gemm1_fused_kernel(const float* __restrict__ b1,
                        const float* __restrict__ W2)
{
    extern __shared__ __align__(16) unsigned char sm[];

    const int tid  = threadIdx.x;
    const int lane = tid & 31;
    const int w    = tid >> 5;
    const int wm   = w & 3;
    const int wn   = w >> 2;
    const int ntile = blockIdx.x;   // 0..3
    const int mtile = blockIdx.y;   // 0..255

    uint32_t sbase = (uint32_t)__cvta_generic_to_shared(&sm[0]);

    auto issue = [&](int stage, int it) {
        uint32_t sa = sbase + stage * STG;
        uint32_t sb = sa + 8192;
        const uint4* gA = g_Xs + ((size_t)(mtile * 32 + it)) * 512;
        const uint4* gB = g_W1s + ((size_t)(it * 4 + ntile)) * 512;
        cp_async16(sa + tid * 16,         gA + tid);
        cp_async16(sa + (tid + 256) * 16, gA + tid + 256);
        cp_async16(sb + tid * 16,         gB + tid);
        cp_async16(sb + (tid + 256) * 16, gB + tid + 256);
    };

    int rA0 = wm * 32 + (lane & 15);
    int rA1 = rA0 + 16;
    int swzA0 = (rA0 & 3) ^ ((rA0 >> 2) & 1);
    int swzA1 = (rA1 & 3) ^ ((rA1 >> 2) & 1);
    int caBase = lane >> 4;
    int kBoff = lane & 15;
    int cbBase = wn * 8 + (lane >> 4);
    int kx = lane & 7;

    float c[2][8][4];
    #pragma unroll
    for (int im = 0; im < 2; im++)
        #pragma unroll
        for (int in = 0; in < 8; in++)
            #pragma unroll
            for (int r = 0; r < 4; r++) c[im][in][r] = 0.f;

    issue(0, 0); cp_commit();
    issue(1, 1); cp_commit();
    issue(2, 2); cp_commit();

    for (int it = 0; it < NIT; ++it) {
        if (it <= NIT - 3)      asm volatile("cp.async.wait_group 2;\n");
        else if (it == NIT - 2) asm volatile("cp.async.wait_group 1;\n");
        else                    asm volatile("cp.async.wait_group 0;\n");
        __syncthreads();

        if (it + 3 < NIT) {
            issue((it + 3) & 3, it + 3);
            cp_commit();
        }

        const int st = it & 3;
        uint32_t abase = sbase + st * STG;
        uint32_t bbase = abase + 8192;

        #pragma unroll
        for (int s = 0; s < 2; s++) {
            uint32_t a[2][4];
            {
                int ch0 = (2 * s + caBase) ^ swzA0;
                int ch1 = (2 * s + caBase) ^ swzA1;
                ldmatrix_x4(a[0], abase + rA0 * 64 + ch0 * 16);
                ldmatrix_x4(a[1], abase + rA1 * 64 + ch1 * 16);
            }
            uint32_t bt[4][4];
            #pragma unroll
            for (int inb = 0; inb < 4; inb++) {
                int ch = (cbBase + inb * 2) ^ kx;
                ldmatrix_x4_trans(bt[inb], bbase + (16 * s + kBoff) * 256 + ch * 16);
            }
            #pragma unroll
            for (int im = 0; im < 2; im++)
                #pragma unroll
                for (int in = 0; in < 8; in++) {
                    uint32_t b0 = bt[in >> 1][(in & 1) * 2];
                    uint32_t b1r = bt[in >> 1][(in & 1) * 2 + 1];
                    mma_bf16(c[im][in], a[im], b0, b1r);
                }
        }
    }
    __syncthreads();

    // ======================= fused epilogue =======================
    const int g  = lane >> 2;
    const int tg = lane & 3;
    const uint32_t hbase = sbase;
    const uint32_t w2b   = sbase + W2_OFF;
    {
        const int nbase = ntile * 128 + wn * 64;
        #pragma unroll
        for (int im = 0; im < 2; im++) {
            #pragma unroll
            for (int in = 0; in < 8; in++) {
                int col = nbase + in * 8 + tg * 2;
                float bias0 = __ldg(&b1[col]);
                float bias1 = __ldg(&b1[col + 1]);
                #pragma unroll
                for (int h = 0; h < 2; h++) {
                    int row = wm * 32 + im * 16 + g + 8 * h;
                    float v0 = c[im][in][2 * h]     + bias0;
                    float v1 = c[im][in][2 * h + 1] + bias1;
                    v0 = 0.5f * v0 * (1.0f + erff(v0 * 0.70710678118654752f));
                    v1 = 0.5f * v1 * (1.0f + erff(v1 * 0.70710678118654752f));
                    __nv_bfloat162 p = __floats2bfloat162_rn(v0, v1);
                    int physu = ((in ^ (row & 7)) + 8 * wn) * 4 + tg;
                    uint32_t addr = hbase + row * 256 + physu * 4;
                    asm volatile("st.shared.b32 [%0], %1;\n"
                                 :: "r"(addr), "r"(*(uint32_t*)&p));
                }
            }
        }
    }
    for (int idx = tid; idx < 128 * 32; idx += 256) {
        int r  = idx >> 5;
        int cc = idx & 31;
        float v = (cc < TT) ? __ldg(&W2[(size_t)(ntile * 128 + r) * TT + cc]) : 0.f;
        __nv_bfloat16 bv = __float2bfloat16(v);
        uint32_t addr = w2b + r * 80 + cc * 2;
        asm volatile("st.shared.b16 [%0], %1;\n"
                     :: "r"(addr), "h"(*(uint16_t*)&bv));
    }
    __syncthreads();

    {
        float e[4][4];
        #pragma unroll
        for (int j = 0; j < 4; j++)
            #pragma unroll
            for (int r = 0; r < 4; r++) e[j][r] = 0.f;

        const int arow = w * 16 + (lane & 15);
        const int asw  = arow & 7;

        #pragma unroll
        for (int k0 = 0; k0 < 128; k0 += 16) {
            uint32_t a[4];
            int ch = ((k0 >> 3) + (lane >> 4)) ^ asw;
            ldmatrix_x4(a, hbase + arow * 256 + ch * 16);
            #pragma unroll
            for (int nt2 = 0; nt2 < 2; nt2++) {
                uint32_t bt[4];
                uint32_t baddr = w2b + (k0 + (lane & 15)) * 80
                               + ((lane >> 4) + 2 * nt2) * 16;
                ldmatrix_x4_trans(bt, baddr);
                mma_bf16(e[nt2 * 2 + 0], a, bt[0], bt[1]);
                mma_bf16(e[nt2 * 2 + 1], a, bt[2], bt[3]);
            }
        }

        float* Ep = g_Ep[ntile];
        #pragma unroll
        for (int j = 0; j < 4; j++) {
            int col = j * 8 + tg * 2;
            #pragma unroll
            for (int h2 = 0; h2 < 2; h2++) {
                int row = mtile * 128 + w * 16 + g + 8 * h2;
                if (col < TT)     Ep[(size_t)row * TT + col]     = e[j][2 * h2];
                if (col + 1 < TT) Ep[(size_t)row * TT + col + 1] = e[j][2 * h2 + 1];
            }
        }
    }
}

// ============================================================================
// reduce: E = sum_k Ep[k] + b2 ; also expE = exp(E)
// ============================================================================
__global__ __launch_bounds__(256)
void reduce_E_kernel(const float* __restrict__ b2)
{
    int i = blockIdx.x * 256 + threadIdx.x;
    if (i < MROWS * TT) {
        float s = g_Ep[0][i] + g_Ep[1][i] + g_Ep[2][i] + g_Ep[3][i];
        float e = s + __ldg(&b2[i % TT]);
        g_E[i] = e;
        g_expE[i] = __expf(e);
    }
}

// ============================================================================
// CRF: linear-domain fwd/bwd scans; per-step broadcast via SMEM (1 STS +
// 7 vectorized LDS.128, double-buffered, ONE syncwarp) instead of 25 SHFLs.
// Weights in 25 named registers.
// ============================================================================
#define FOREACH_W(F) \
    F(0)  F(1)  F(2)  F(3)  F(4)  F(5)  F(6)  F(7)  F(8)  F(9)  \
    F(10) F(11) F(12) F(13) F(14) F(15) F(16) F(17) F(18) F(19) \
    F(20) F(21) F(22) F(23) F(24)

#define DECL_W(i)  float w##i;
#define LOAD_W(i)  w##i = __expf(trans_sh[wrow ? (rc * TT + i) : (i * TT + rc)]);

// dot of psh[0..24] (padded to 28, pad=0) with w0..w24 via 7 float4 loads
#define DOT25_SMEM(pb, out) do {                                  \
    float4 _v0 = *(const float4*)((pb) + 0);                      \
    float4 _v1 = *(const float4*)((pb) + 4);                      \
    float4 _v2 = *(const float4*)((pb) + 8);                      \
    float4 _v3 = *(const float4*)((pb) + 12);                     \
    float4 _v4 = *(const float4*)((pb) + 16);                     \
    float4 _v5 = *(const float4*)((pb) + 20);                     \
    float4 _v6 = *(const float4*)((pb) + 24);                     \
    float _a0 = _v0.x * w0;                                       \
    float _a1 = _v0.y * w1;                                       \
    float _a2 = _v0.z * w2;                                       \
    float _a3 = _v0.w * w3;                                       \
    _a0 = fmaf(_v1.x, w4,  _a0);                                  \
    _a1 = fmaf(_v1.y, w5,  _a1);                                  \
    _a2 = fmaf(_v1.z, w6,  _a2);                                  \
    _a3 = fmaf(_v1.w, w7,  _a3);                                  \
    _a0 = fmaf(_v2.x, w8,  _a0);                                  \
    _a1 = fmaf(_v2.y, w9,  _a1);                                  \
    _a2 = fmaf(_v2.z, w10, _a2);                                  \
    _a3 = fmaf(_v2.w, w11, _a3);                                  \
    _a0 = fmaf(_v3.x, w12, _a0);                                  \
    _a1 = fmaf(_v3.y, w13, _a1);                                  \
    _a2 = fmaf(_v3.z, w14, _a2);                                  \
    _a3 = fmaf(_v3.w, w15, _a3);                                  \
    _a0 = fmaf(_v4.x, w16, _a0);                                  \
    _a1 = fmaf(_v4.y, w17, _a1);                                  \
    _a2 = fmaf(_v4.z, w18, _a2);                                  \
    _a3 = fmaf(_v4.w, w19, _a3);                                  \
    _a0 = fmaf(_v5.x, w20, _a0);                                  \
    _a1 = fmaf(_v5.y, w21, _a1);                                  \
    _a2 = fmaf(_v5.z, w22, _a2);                                  \
    _a3 = fmaf(_v5.w, w23, _a3);                                  \
    _a0 = fmaf(_v6.x, w24, _a0);                                  \
    (out) = (_a0 + _a1) + (_a2 + _a3);                            \
} while (0)

// shfl-based matvec (fallback path only)
#define MATVEC25(src, out) do {                                   \
    float _a0, _a1, _a2, _a3;                                     \
    _a0 = __shfl_sync(full, (src), 0)  * w0;                      \
    _a1 = __shfl_sync(full, (src), 1)  * w1;                      \
    _a2 = __shfl_sync(full, (src), 2)  * w2;                      \
    _a3 = __shfl_sync(full, (src), 3)  * w3;                      \
    _a0 = fmaf(__shfl_sync(full, (src), 4),  w4,  _a0);           \
    _a1 = fmaf(__shfl_sync(full, (src), 5),  w5,  _a1);           \
    _a2 = fmaf(__shfl_sync(full, (src), 6),  w6,  _a2);           \
    _a3 = fmaf(__shfl_sync(full, (src), 7),  w7,  _a3);           \
    _a0 = fmaf(__shfl_sync(full, (src), 8),  w8,  _a0);           \
    _a1 = fmaf(__shfl_sync(full, (src), 9),  w9,  _a1);           \
    _a2 = fmaf(__shfl_sync(full, (src), 10), w10, _a2);           \
    _a3 = fmaf(__shfl_sync(full, (src), 11), w11, _a3);           \
    _a0 = fmaf(__shfl_sync(full, (src), 12), w12, _a0);           \
    _a1 = fmaf(__shfl_sync(full, (src), 13), w13, _a1);           \
    _a2 = fmaf(__shfl_sync(full, (src), 14), w14, _a2);           \
    _a3 = fmaf(__shfl_sync(full, (src), 15), w15, _a3);           \
    _a0 = fmaf(__shfl_sync(full, (src), 16), w16, _a0);           \
    _a1 = fmaf(__shfl_sync(full, (src), 17), w17, _a1);           \
    _a2 = fmaf(__shfl_sync(full, (src), 18), w18, _a2);           \
    _a3 = fmaf(__shfl_sync(full, (src), 19), w19, _a3);           \
    _a0 = fmaf(__shfl_sync(full, (src), 20), w20, _a0);           \
    _a1 = fmaf(__shfl_sync(full, (src), 21), w21, _a1);           \
    _a2 = fmaf(__shfl_sync(full, (src), 22), w22, _a2);           \
    _a3 = fmaf(__shfl_sync(full, (src), 23), w23, _a3);           \
    _a0 = fmaf(__shfl_sync(full, (src), 24), w24, _a0);           \
    (out) = (_a0 + _a1) + (_a2 + _a3);                            \
} while (0)

__global__ __launch_bounds__(64)
void crf_kernel(const float* __restrict__ start_t,
                const float* __restrict__ end_t,
                const float* __restrict__ trans,
                const void*  __restrict__ labels_raw,
                const void*  __restrict__ mask_raw)
{
    __shared__ float trans_sh[TT * TT];
    __shared__ unsigned char msh[SS];
    __shared__ float comb[64];
    __shared__ float nacc[2];
    __shared__ int   ncnt[2];
    __shared__ __align__(16) float psh[2][2][32];   // [warp][buf][lane]

    const int b = blockIdx.x;
    const int tid = threadIdx.x;      // 0..63
    const int lane = tid & 31;
    const int warp = tid >> 5;
    const unsigned full = 0xffffffffu;

    for (int i = tid; i < TT * TT; i += 64) trans_sh[i] = trans[i];

    // ---- label dtype detect ----
    const int* li = (const int*)labels_raw;
    unsigned ball = __ballot_sync(full, li[2 * lane + 1] == 0);
    const int lstride = (ball == full) ? 2 : 1;

    // ---- mask encoding detect ----
    const unsigned* mw = (const unsigned*)mask_raw;
    unsigned any_high = 0, any_float = 0;
    for (int i = lane; i < 256; i += 32) {
        unsigned wv = mw[i];
        any_float |= (wv == 0x3F800000u);
        any_high  |= (wv & 0xFFFFFF00u) && (wv != 0x3F800000u);
    }
    const bool is_float = __ballot_sync(full, any_float != 0) != 0;
    const bool is_byte  = !is_float && (__ballot_sync(full, any_high != 0) != 0);

    const int base = b * SS;

    int myok = 1;
    for (int t = tid; t < SS; t += 64) {
        unsigned char mv;
        if (is_float)      mv = (((const float*)mask_raw)[base + t] != 0.f);
        else if (is_byte)  mv = (((const unsigned char*)mask_raw)[base + t] != 0);
        else               mv = (((const int*)mask_raw)[base + t] != 0);
        msh[t] = mv;
        myok &= mv;
    }
    const int allones = __syncthreads_and(myok);

    const float* Eb  = g_E    + (size_t)base * TT;
    const float* Xb  = g_expE + (size_t)base * TT;

    // ---- numerator partials (both warps, 64-strided) ----
    float acc = 0.f;
    int cnt = 0;
    for (int t = tid; t < SS; t += 64) cnt += msh[t];
    for (int t = 1 + tid; t < SS; t += 64) {
        if (msh[t]) {
            int lt = li[(base + t) * lstride];
            int lp = li[(base + t - 1) * lstride];
            acc += trans_sh[lp * TT + lt] + Eb[t * TT + lt];
        }
    }
    #pragma unroll
    for (int off = 16; off > 0; off >>= 1) {
        acc += __shfl_xor_sync(full, acc, off);
        cnt += __shfl_xor_sync(full, cnt, off);
    }
    if (lane == 0) { nacc[warp] = acc; ncnt[warp] = cnt; }

    // ---- 25 named weight registers: exp(trans) col (fwd) / row (bwd) ----
    const int rc = (lane < TT) ? lane : (TT - 1);
    const int wrow = warp;
    FOREACH_W(DECL_W)
    FOREACH_W(LOAD_W)

    if (allones) {
        float* pb0 = &psh[warp][0][0];
        float* pb1 = &psh[warp][1][0];
        // zero pad lanes 25..31 once (we always store masked values anyway)
        psh[warp][0][lane] = 0.f;
        psh[warp][1][lane] = 0.f;
        __syncwarp();

        if (warp == 0) {
            // forward, linear domain: A_t = expE_t * (W^T A_{t-1})
            float p = (lane < TT) ? __expf(start_t[lane] + Eb[lane]) : 0.f;
            float logS = 0.f;
            float e_next = (lane < TT) ? Xb[1 * TT + lane] : 0.f;
            for (int t = 1; t <= 256; t++) {
                float e_cur = e_next;
                if (t < 256) e_next = (lane < TT) ? Xb[(t + 1) * TT + lane] : 0.f;
                float* pb = (t & 1) ? pb0 : pb1;
                pb[lane] = (lane < TT) ? p : 0.f;
                __syncwarp();
                float s;
                DOT25_SMEM(pb, s);
                p = s * e_cur;
                if ((t & 15) == 0) {
                    float cc = __shfl_sync(full, p, 0);
                    p *= (1.0f / cc);
                    logS += __logf(cc);
                }
            }
            comb[lane] = (lane < TT) ? (__logf(p) + logS) : -INFINITY;
        } else {
            // backward, linear domain: B_{t-1} = W (expE_t ⊙ B_t)
            float p = (lane < TT) ? __expf(end_t[lane]) : 0.f;
            float logS = 0.f;
            float e_next = (lane < TT) ? Xb[511 * TT + lane] : 0.f;
            for (int t = 511; t >= 257; t--) {
                float e_cur = e_next;
                if (t > 257) e_next = (lane < TT) ? Xb[(t - 1) * TT + lane] : 0.f;
                float q = p * e_cur;
                float* pb = (t & 1) ? pb0 : pb1;
                pb[lane] = (lane < TT) ? q : 0.f;
                __syncwarp();
                DOT25_SMEM(pb, p);
                if ((t & 15) == 0) {
                    float cc = __shfl_sync(full, p, 0);
                    p *= (1.0f / cc);
                    logS += __logf(cc);
                }
            }
            comb[32 + lane] = (lane < TT) ? (__logf(p) + logS) : -INFINITY;
        }
        __syncthreads();

        if (warp == 0) {
            float v = (lane < TT) ? (comb[lane] + comb[32 + lane]) : -INFINITY;
            float M2 = v;
            #pragma unroll
            for (int off = 16; off > 0; off >>= 1)
                M2 = fmaxf(M2, __shfl_xor_sync(full, M2, off));
            float s2 = (lane < TT) ? __expf(v - M2) : 0.f;
            #pragma unroll
            for (int off = 16; off > 0; off >>= 1)
                s2 += __shfl_xor_sync(full, s2, off);

            if (lane == 0) {
                int lab0 = li[base * lstride];
                float score0 = start_t[lab0] + Eb[lab0];
                int last_tag = li[(base + SS - 1) * lstride];
                float numerator = score0 + (nacc[0] + nacc[1]) + end_t[last_tag];
                float logZ = M2 + __logf(s2);
                g_ll[b] = numerator - logZ;
            }
        }
    } else {
        // -------- fallback: serial masked log-domain scan in warp 0 --------
        __syncthreads();
        if (warp == 0) {
            float alpha = (lane < TT) ? (start_t[lane] + Eb[lane]) : -INFINITY;
            float e_next = (lane < TT) ? Eb[1 * TT + lane] : 0.f;
            unsigned char m_next = msh[1];
            for (int t = 1; t < SS; t++) {
                float e_cur = e_next;
                unsigned char m_cur = m_next;
                if (t + 1 < SS) {
                    e_next = (lane < TT) ? Eb[(t + 1) * TT + lane] : 0.f;
                    m_next = msh[t + 1];
                }
                float M = __shfl_sync(full, alpha, 0);
                float p = __expf(alpha - M);
                float s;
                MATVEC25(p, s);
                float nv = e_cur + M + __logf(s);
                if (lane < TT && m_cur) alpha = nv;
            }
            float v = (lane < TT) ? (alpha + end_t[lane]) : -INFINITY;
            float M2 = v;
            #pragma unroll
            for (int off = 16; off > 0; off >>= 1)
                M2 = fmaxf(M2, __shfl_xor_sync(full, M2, off));
            float s2 = (lane < TT) ? __expf(v - M2) : 0.f;
            #pragma unroll
            for (int off = 16; off > 0; off >>= 1)
                s2 += __shfl_xor_sync(full, s2, off);

            if (lane == 0) {
                int lab0 = li[base * lstride];
                float score0 = start_t[lab0] + Eb[lab0];
                int last_idx = (ncnt[0] + ncnt[1]) - 1;
                int last_tag = li[(base + last_idx) * lstride];
                float numerator = score0 + (nacc[0] + nacc[1]) + end_t[last_tag];
                float logZ = M2 + __logf(s2);
                g_ll[b] = numerator - logZ;
            }
        }
    }
}

// ============================================================================
// finalize: out = -mean(ll)
// ============================================================================
__global__ void finalize_kernel(float* __restrict__ out)
{
    __shared__ float sbuf[2];
    const int l = threadIdx.x; // 64 threads
    float v = g_ll[l];
    #pragma unroll
    for (int off = 16; off > 0; off >>= 1)
        v += __shfl_xor_sync(0xffffffffu, v, off);
    if ((l & 31) == 0) sbuf[l >> 5] = v;
    __syncthreads();
    if (l == 0) out[0] = -(sbuf[0] + sbuf[1]) / (float)BB;
}

// ============================================================================
// launch  (crf at index 3 -> profiled)
// ============================================================================
extern "C" void kernel_launch(void* const* d_in, const int* in_sizes, int n_in,
                              void* d_out, int out_size)
{
    const float* X       = (const float*)d_in[0];
    const float* W1      = (const float*)d_in[1];
    const float* b1      = (const float*)d_in[2];
    const float* W2      = (const float*)d_in[3];
    const float* b2      = (const float*)d_in[4];
    const float* start_t = (const float*)d_in[5];
    const float* end_t   = (const float*)d_in[6];
    const float* trans   = (const float*)d_in[7];
    const void*  labels  = d_in[8];
    const void*  mask    = d_in[9];
    float* out = (float*)d_out;

    convert_all_kernel<<<XBLOCKS + WBLOCKS, 256>>>(X, W1);

    cudaFuncSetAttribute(gemm1_fused_kernel,
                         cudaFuncAttributeMaxDynamicSharedMemorySize, SMEM_DYN);
    dim3 g1(HH / 128, MROWS / 128);
    gemm1_fused_kernel<<<g1, 256, SMEM_DYN>>>(b1, W2);

    reduce_E_kernel<<<(MROWS * TT + 255) / 256, 256>>>(b2);

    crf_kernel<<<BB, 64>>>(start_t, end_t, trans, labels, mask);

    finalize_kernel<<<1, 64>>>(out);
}

// round 15
// speedup vs baseline: 1.2026x; 1.1794x over previous
#include <cuda_runtime.h>
#include <cuda_bf16.h>
#include <math.h>
#include <stdint.h>

// Problem constants
#define BB   64
#define SS   512
#define DD   1024
#define HH   512
#define TT   25
#define MROWS (BB*SS)          // 32768

// -------- scratch (allocation-free: __device__ globals) --------
__device__ uint4 g_Xs[(size_t)MROWS * DD / 8];   // 64 MB bf16 X, tiled+swizzled
__device__ uint4 g_W1s[(size_t)DD * HH / 8];     // 1 MB bf16 W1, tiled+swizzled
__device__ float g_Ep[4][(size_t)MROWS * TT];    // split-K emission partials
__device__ float g_E[(size_t)MROWS * TT + 32];   // emissions (+pad)
__device__ float g_expE[(size_t)MROWS * TT + 32];// exp(emissions) (+pad)
__device__ float g_ll[BB];                       // per-batch log-likelihood

// ============================================================================
// convert_all: X -> bf16 tiles (blocks 0..16383), W1 -> bf16 tiles (the rest)
// ============================================================================
#define XBLOCKS ((MROWS * DD / 8) / 256)   // 16384
#define WBLOCKS ((DD * HH / 8) / 256)      // 256

__global__ __launch_bounds__(256)
void convert_all_kernel(const float* __restrict__ X,
                        const float* __restrict__ W1)
{
    if (blockIdx.x < XBLOCKS) {
        int id = blockIdx.x * 256 + threadIdx.x;
        int tile   = id >> 9;
        int within = id & 511;
        int r  = within >> 2;
        int cp = within & 3;
        int mtile = tile >> 5;
        int ktile = tile & 31;
        int sw = (r & 3) ^ ((r >> 2) & 1);
        int c  = cp ^ sw;
        int m = mtile * 128 + r;
        int k = ktile * 32 + c * 8;
        const float4* src = (const float4*)(X + (size_t)m * DD + k);
        float4 x0 = src[0], x1 = src[1];
        __nv_bfloat162 p0 = __floats2bfloat162_rn(x0.x, x0.y);
        __nv_bfloat162 p1 = __floats2bfloat162_rn(x0.z, x0.w);
        __nv_bfloat162 p2 = __floats2bfloat162_rn(x1.x, x1.y);
        __nv_bfloat162 p3 = __floats2bfloat162_rn(x1.z, x1.w);
        uint4 out;
        out.x = *(uint32_t*)&p0; out.y = *(uint32_t*)&p1;
        out.z = *(uint32_t*)&p2; out.w = *(uint32_t*)&p3;
        g_Xs[id] = out;
    } else {
        int id = (blockIdx.x - XBLOCKS) * 256 + threadIdx.x;
        int tile   = id >> 9;
        int within = id & 511;
        int k  = within >> 4;
        int cp = within & 15;
        int ktile = tile >> 2;
        int ntile = tile & 3;
        int c = cp ^ (k & 7);
        int krow = ktile * 32 + k;
        int n = ntile * 128 + c * 8;
        const float4* src = (const float4*)(W1 + (size_t)krow * HH + n);
        float4 x0 = src[0], x1 = src[1];
        __nv_bfloat162 p0 = __floats2bfloat162_rn(x0.x, x0.y);
        __nv_bfloat162 p1 = __floats2bfloat162_rn(x0.z, x0.w);
        __nv_bfloat162 p2 = __floats2bfloat162_rn(x1.x, x1.y);
        __nv_bfloat162 p3 = __floats2bfloat162_rn(x1.z, x1.w);
        uint4 out;
        out.x = *(uint32_t*)&p0; out.y = *(uint32_t*)&p1;
        out.z = *(uint32_t*)&p2; out.w = *(uint32_t*)&p3;
        g_W1s[id] = out;
    }
}

// ============================================================================
// GEMM1 (tensor cores): H = gelu(X @ W1 + b1), fused GEMM2 partials
// ============================================================================
#define NIT (DD / 32)   // 32 k-iterations
#define STG 16384       // per stage: 8KB A + 8KB B
#define SMEM_DYN (4 * STG)
#define W2_OFF  49152

__device__ __forceinline__ void cp_async16(uint32_t saddr, const void* gaddr) {
    asm volatile("cp.async.cg.shared.global [%0], [%1], 16;\n"
                 :: "r"(saddr), "l"(gaddr));
}
__device__ __forceinline__ void cp_commit() {
    asm volatile("cp.async.commit_group;\n");
}
__device__ __forceinline__ void ldmatrix_x4(uint32_t* r, uint32_t addr) {
    asm volatile("ldmatrix.sync.aligned.m8n8.x4.shared.b16 {%0,%1,%2,%3}, [%4];"
                 : "=r"(r[0]), "=r"(r[1]), "=r"(r[2]), "=r"(r[3]) : "r"(addr));
}
__device__ __forceinline__ void ldmatrix_x4_trans(uint32_t* r, uint32_t addr) {
    asm volatile("ldmatrix.sync.aligned.m8n8.x4.trans.shared.b16 {%0,%1,%2,%3}, [%4];"
                 : "=r"(r[0]), "=r"(r[1]), "=r"(r[2]), "=r"(r[3]) : "r"(addr));
}
__device__ __forceinline__ void mma_bf16(float* c, const uint32_t* a,
                                         uint32_t b0, uint32_t b1) {
    asm volatile("mma.sync.aligned.m16n8k16.row.col.f32.bf16.bf16.f32 "
                 "{%0,%1,%2,%3},{%4,%5,%6,%7},{%8,%9},{%0,%1,%2,%3};"
                 : "+f"(c[0]), "+f"(c[1]), "+f"(c[2]), "+f"(c[3])
                 : "r"(a[0]), "r"(a[1]), "r"(a[2]), "r"(a[3]), "r"(b0), "r"(b1));
}

__global__ __launch_bounds__(256)
void gemm1_fused_kernel(const float* __restrict__ b1,
                        const float* __restrict__ W2)
{
    extern __shared__ __align__(16) unsigned char sm[];

    const int tid  = threadIdx.x;
    const int lane = tid & 31;
    const int w    = tid >> 5;
    const int wm   = w & 3;
    const int wn   = w >> 2;
    const int ntile = blockIdx.x;   // 0..3
    const int mtile = blockIdx.y;   // 0..255

    uint32_t sbase = (uint32_t)__cvta_generic_to_shared(&sm[0]);

    auto issue = [&](int stage, int it) {
        uint32_t sa = sbase + stage * STG;
        uint32_t sb = sa + 8192;
        const uint4* gA = g_Xs + ((size_t)(mtile * 32 + it)) * 512;
        const uint4* gB = g_W1s + ((size_t)(it * 4 + ntile)) * 512;
        cp_async16(sa + tid * 16,         gA + tid);
        cp_async16(sa + (tid + 256) * 16, gA + tid + 256);
        cp_async16(sb + tid * 16,         gB + tid);
        cp_async16(sb + (tid + 256) * 16, gB + tid + 256);
    };

    int rA0 = wm * 32 + (lane & 15);
    int rA1 = rA0 + 16;
    int swzA0 = (rA0 & 3) ^ ((rA0 >> 2) & 1);
    int swzA1 = (rA1 & 3) ^ ((rA1 >> 2) & 1);
    int caBase = lane >> 4;
    int kBoff = lane & 15;
    int cbBase = wn * 8 + (lane >> 4);
    int kx = lane & 7;

    float c[2][8][4];
    #pragma unroll
    for (int im = 0; im < 2; im++)
        #pragma unroll
        for (int in = 0; in < 8; in++)
            #pragma unroll
            for (int r = 0; r < 4; r++) c[im][in][r] = 0.f;

    issue(0, 0); cp_commit();
    issue(1, 1); cp_commit();
    issue(2, 2); cp_commit();

    for (int it = 0; it < NIT; ++it) {
        if (it <= NIT - 3)      asm volatile("cp.async.wait_group 2;\n");
        else if (it == NIT - 2) asm volatile("cp.async.wait_group 1;\n");
        else                    asm volatile("cp.async.wait_group 0;\n");
        __syncthreads();

        if (it + 3 < NIT) {
            issue((it + 3) & 3, it + 3);
            cp_commit();
        }

        const int st = it & 3;
        uint32_t abase = sbase + st * STG;
        uint32_t bbase = abase + 8192;

        #pragma unroll
        for (int s = 0; s < 2; s++) {
            uint32_t a[2][4];
            {
                int ch0 = (2 * s + caBase) ^ swzA0;
                int ch1 = (2 * s + caBase) ^ swzA1;
                ldmatrix_x4(a[0], abase + rA0 * 64 + ch0 * 16);
                ldmatrix_x4(a[1], abase + rA1 * 64 + ch1 * 16);
            }
            uint32_t bt[4][4];
            #pragma unroll
            for (int inb = 0; inb < 4; inb++) {
                int ch = (cbBase + inb * 2) ^ kx;
                ldmatrix_x4_trans(bt[inb], bbase + (16 * s + kBoff) * 256 + ch * 16);
            }
            #pragma unroll
            for (int im = 0; im < 2; im++)
                #pragma unroll
                for (int in = 0; in < 8; in++) {
                    uint32_t b0 = bt[in >> 1][(in & 1) * 2];
                    uint32_t b1r = bt[in >> 1][(in & 1) * 2 + 1];
                    mma_bf16(c[im][in], a[im], b0, b1r);
                }
        }
    }
    __syncthreads();

    // ======================= fused epilogue =======================
    const int g  = lane >> 2;
    const int tg = lane & 3;
    const uint32_t hbase = sbase;
    const uint32_t w2b   = sbase + W2_OFF;
    {
        const int nbase = ntile * 128 + wn * 64;
        #pragma unroll
        for (int im = 0; im < 2; im++) {
            #pragma unroll
            for (int in = 0; in < 8; in++) {
                int col = nbase + in * 8 + tg * 2;
                float bias0 = __ldg(&b1[col]);
                float bias1 = __ldg(&b1[col + 1]);
                #pragma unroll
                for (int h = 0; h < 2; h++) {
                    int row = wm * 32 + im * 16 + g + 8 * h;
                    float v0 = c[im][in][2 * h]     + bias0;
                    float v1 = c[im][in][2 * h + 1] + bias1;
                    v0 = 0.5f * v0 * (1.0f + erff(v0 * 0.70710678118654752f));
                    v1 = 0.5f * v1 * (1.0f + erff(v1 * 0.70710678118654752f));
                    __nv_bfloat162 p = __floats2bfloat162_rn(v0, v1);
                    int physu = ((in ^ (row & 7)) + 8 * wn) * 4 + tg;
                    uint32_t addr = hbase + row * 256 + physu * 4;
                    asm volatile("st.shared.b32 [%0], %1;\n"
                                 :: "r"(addr), "r"(*(uint32_t*)&p));
                }
            }
        }
    }
    for (int idx = tid; idx < 128 * 32; idx += 256) {
        int r  = idx >> 5;
        int cc = idx & 31;
        float v = (cc < TT) ? __ldg(&W2[(size_t)(ntile * 128 + r) * TT + cc]) : 0.f;
        __nv_bfloat16 bv = __float2bfloat16(v);
        uint32_t addr = w2b + r * 80 + cc * 2;
        asm volatile("st.shared.b16 [%0], %1;\n"
                     :: "r"(addr), "h"(*(uint16_t*)&bv));
    }
    __syncthreads();

    {
        float e[4][4];
        #pragma unroll
        for (int j = 0; j < 4; j++)
            #pragma unroll
            for (int r = 0; r < 4; r++) e[j][r] = 0.f;

        const int arow = w * 16 + (lane & 15);
        const int asw  = arow & 7;

        #pragma unroll
        for (int k0 = 0; k0 < 128; k0 += 16) {
            uint32_t a[4];
            int ch = ((k0 >> 3) + (lane >> 4)) ^ asw;
            ldmatrix_x4(a, hbase + arow * 256 + ch * 16);
            #pragma unroll
            for (int nt2 = 0; nt2 < 2; nt2++) {
                uint32_t bt[4];
                uint32_t baddr = w2b + (k0 + (lane & 15)) * 80
                               + ((lane >> 4) + 2 * nt2) * 16;
                ldmatrix_x4_trans(bt, baddr);
                mma_bf16(e[nt2 * 2 + 0], a, bt[0], bt[1]);
                mma_bf16(e[nt2 * 2 + 1], a, bt[2], bt[3]);
            }
        }

        float* Ep = g_Ep[ntile];
        #pragma unroll
        for (int j = 0; j < 4; j++) {
            int col = j * 8 + tg * 2;
            #pragma unroll
            for (int h2 = 0; h2 < 2; h2++) {
                int row = mtile * 128 + w * 16 + g + 8 * h2;
                if (col < TT)     Ep[(size_t)row * TT + col]     = e[j][2 * h2];
                if (col + 1 < TT) Ep[(size_t)row * TT + col + 1] = e[j][2 * h2 + 1];
            }
        }
    }
}

// ============================================================================
// reduce: E = sum_k Ep[k] + b2 ; also expE = exp(E)
// ============================================================================
__global__ __launch_bounds__(256)
void reduce_E_kernel(const float* __restrict__ b2)
{
    int i = blockIdx.x * 256 + threadIdx.x;
    if (i < MROWS * TT) {
        float s = g_Ep[0][i] + g_Ep[1][i] + g_Ep[2][i] + g_Ep[3][i];
        float e = s + __ldg(&b2[i % TT]);
        g_E[i] = e;
        g_expE[i] = __expf(e);
    }
}

// ============================================================================
// CRF: linear-domain fwd/bwd scans. The batch's full expE slice (512x25 fp32,
// 51.3KB) is staged into DYNAMIC SMEM in a coalesced prologue so the scan loop
// never touches global memory. Broadcast via double-buffered smem + LDS.128.
// ============================================================================
#define FOREACH_W(F) \
    F(0)  F(1)  F(2)  F(3)  F(4)  F(5)  F(6)  F(7)  F(8)  F(9)  \
    F(10) F(11) F(12) F(13) F(14) F(15) F(16) F(17) F(18) F(19) \
    F(20) F(21) F(22) F(23) F(24)

#define DECL_W(i)  float w##i;
#define LOAD_W(i)  w##i = __expf(trans_sh[wrow ? (rc * TT + i) : (i * TT + rc)]);

#define DOT25_SMEM(pb, out) do {                                  \
    float4 _v0 = *(const float4*)((pb) + 0);                      \
    float4 _v1 = *(const float4*)((pb) + 4);                      \
    float4 _v2 = *(const float4*)((pb) + 8);                      \
    float4 _v3 = *(const float4*)((pb) + 12);                     \
    float4 _v4 = *(const float4*)((pb) + 16);                     \
    float4 _v5 = *(const float4*)((pb) + 20);                     \
    float4 _v6 = *(const float4*)((pb) + 24);                     \
    float _a0 = _v0.x * w0;                                       \
    float _a1 = _v0.y * w1;                                       \
    float _a2 = _v0.z * w2;                                       \
    float _a3 = _v0.w * w3;                                       \
    _a0 = fmaf(_v1.x, w4,  _a0);                                  \
    _a1 = fmaf(_v1.y, w5,  _a1);                                  \
    _a2 = fmaf(_v1.z, w6,  _a2);                                  \
    _a3 = fmaf(_v1.w, w7,  _a3);                                  \
    _a0 = fmaf(_v2.x, w8,  _a0);                                  \
    _a1 = fmaf(_v2.y, w9,  _a1);                                  \
    _a2 = fmaf(_v2.z, w10, _a2);                                  \
    _a3 = fmaf(_v2.w, w11, _a3);                                  \
    _a0 = fmaf(_v3.x, w12, _a0);                                  \
    _a1 = fmaf(_v3.y, w13, _a1);                                  \
    _a2 = fmaf(_v3.z, w14, _a2);                                  \
    _a3 = fmaf(_v3.w, w15, _a3);                                  \
    _a0 = fmaf(_v4.x, w16, _a0);                                  \
    _a1 = fmaf(_v4.y, w17, _a1);                                  \
    _a2 = fmaf(_v4.z, w18, _a2);                                  \
    _a3 = fmaf(_v4.w, w19, _a3);                                  \
    _a0 = fmaf(_v5.x, w20, _a0);                                  \
    _a1 = fmaf(_v5.y, w21, _a1);                                  \
    _a2 = fmaf(_v5.z, w22, _a2);                                  \
    _a3 = fmaf(_v5.w, w23, _a3);                                  \
    _a0 = fmaf(_v6.x, w24, _a0);                                  \
    (out) = (_a0 + _a1) + (_a2 + _a3);                            \
} while (0)

#define MATVEC25(src, out) do {                                   \
    float _a0, _a1, _a2, _a3;                                     \
    _a0 = __shfl_sync(full, (src), 0)  * w0;                      \
    _a1 = __shfl_sync(full, (src), 1)  * w1;                      \
    _a2 = __shfl_sync(full, (src), 2)  * w2;                      \
    _a3 = __shfl_sync(full, (src), 3)  * w3;                      \
    _a0 = fmaf(__shfl_sync(full, (src), 4),  w4,  _a0);           \
    _a1 = fmaf(__shfl_sync(full, (src), 5),  w5,  _a1);           \
    _a2 = fmaf(__shfl_sync(full, (src), 6),  w6,  _a2);           \
    _a3 = fmaf(__shfl_sync(full, (src), 7),  w7,  _a3);           \
    _a0 = fmaf(__shfl_sync(full, (src), 8),  w8,  _a0);           \
    _a1 = fmaf(__shfl_sync(full, (src), 9),  w9,  _a1);           \
    _a2 = fmaf(__shfl_sync(full, (src), 10), w10, _a2);           \
    _a3 = fmaf(__shfl_sync(full, (src), 11), w11, _a3);           \
    _a0 = fmaf(__shfl_sync(full, (src), 12), w12, _a0);           \
    _a1 = fmaf(__shfl_sync(full, (src), 13), w13, _a1);           \
    _a2 = fmaf(__shfl_sync(full, (src), 14), w14, _a2);           \
    _a3 = fmaf(__shfl_sync(full, (src), 15), w15, _a3);           \
    _a0 = fmaf(__shfl_sync(full, (src), 16), w16, _a0);           \
    _a1 = fmaf(__shfl_sync(full, (src), 17), w17, _a1);           \
    _a2 = fmaf(__shfl_sync(full, (src), 18), w18, _a2);           \
    _a3 = fmaf(__shfl_sync(full, (src), 19), w19, _a3);           \
    _a0 = fmaf(__shfl_sync(full, (src), 20), w20, _a0);           \
    _a1 = fmaf(__shfl_sync(full, (src), 21), w21, _a1);           \
    _a2 = fmaf(__shfl_sync(full, (src), 22), w22, _a2);           \
    _a3 = fmaf(__shfl_sync(full, (src), 23), w23, _a3);           \
    _a0 = fmaf(__shfl_sync(full, (src), 24), w24, _a0);           \
    (out) = (_a0 + _a1) + (_a2 + _a3);                            \
} while (0)

#define CRF_SMEM ((SS * TT + 32) * 4)   // 51328 B dynamic: expE slice + pad

__global__ __launch_bounds__(64)
void crf_kernel(const float* __restrict__ start_t,
                const float* __restrict__ end_t,
                const float* __restrict__ trans,
                const void*  __restrict__ labels_raw,
                const void*  __restrict__ mask_raw)
{
    extern __shared__ __align__(16) float e_sh[];   // [SS*TT + pad]
    __shared__ float trans_sh[TT * TT];
    __shared__ unsigned char msh[SS];
    __shared__ float comb[64];
    __shared__ float nacc[2];
    __shared__ int   ncnt[2];
    __shared__ __align__(16) float psh[2][2][32];   // [warp][buf][lane]

    const int b = blockIdx.x;
    const int tid = threadIdx.x;      // 0..63
    const int lane = tid & 31;
    const int warp = tid >> 5;
    const unsigned full = 0xffffffffu;

    for (int i = tid; i < TT * TT; i += 64) trans_sh[i] = trans[i];

    // ---- label dtype detect ----
    const int* li = (const int*)labels_raw;
    unsigned ball = __ballot_sync(full, li[2 * lane + 1] == 0);
    const int lstride = (ball == full) ? 2 : 1;

    // ---- mask encoding detect ----
    const unsigned* mw = (const unsigned*)mask_raw;
    unsigned any_high = 0, any_float = 0;
    for (int i = lane; i < 256; i += 32) {
        unsigned wv = mw[i];
        any_float |= (wv == 0x3F800000u);
        any_high  |= (wv & 0xFFFFFF00u) && (wv != 0x3F800000u);
    }
    const bool is_float = __ballot_sync(full, any_float != 0) != 0;
    const bool is_byte  = !is_float && (__ballot_sync(full, any_high != 0) != 0);

    const int base = b * SS;

    int myok = 1;
    for (int t = tid; t < SS; t += 64) {
        unsigned char mv;
        if (is_float)      mv = (((const float*)mask_raw)[base + t] != 0.f);
        else if (is_byte)  mv = (((const unsigned char*)mask_raw)[base + t] != 0);
        else               mv = (((const int*)mask_raw)[base + t] != 0);
        msh[t] = mv;
        myok &= mv;
    }

    const float* Eb  = g_E    + (size_t)base * TT;
    const float* Xb  = g_expE + (size_t)base * TT;

    // ---- stage expE slice into dynamic smem (coalesced float4) ----
    {
        const float4* src4 = (const float4*)Xb;     // 3200 float4
        float4* dst4 = (float4*)e_sh;
        #pragma unroll 4
        for (int i = tid; i < (SS * TT) / 4; i += 64) dst4[i] = src4[i];
        if (tid < 32) e_sh[SS * TT + tid] = 0.f;    // pad
    }
    const int allones = __syncthreads_and(myok);    // also fences e_sh fill

    // ---- numerator partials (both warps, 64-strided) ----
    float acc = 0.f;
    int cnt = 0;
    for (int t = tid; t < SS; t += 64) cnt += msh[t];
    for (int t = 1 + tid; t < SS; t += 64) {
        if (msh[t]) {
            int lt = li[(base + t) * lstride];
            int lp = li[(base + t - 1) * lstride];
            acc += trans_sh[lp * TT + lt] + Eb[t * TT + lt];
        }
    }
    #pragma unroll
    for (int off = 16; off > 0; off >>= 1) {
        acc += __shfl_xor_sync(full, acc, off);
        cnt += __shfl_xor_sync(full, cnt, off);
    }
    if (lane == 0) { nacc[warp] = acc; ncnt[warp] = cnt; }

    // ---- 25 named weight registers: exp(trans) col (fwd) / row (bwd) ----
    const int rc = (lane < TT) ? lane : (TT - 1);
    const int wrow = warp;
    FOREACH_W(DECL_W)
    FOREACH_W(LOAD_W)

    if (allones) {
        float* pb0 = &psh[warp][0][0];
        float* pb1 = &psh[warp][1][0];
        psh[warp][0][lane] = 0.f;
        psh[warp][1][lane] = 0.f;
        __syncwarp();

        if (warp == 0) {
            // forward, linear domain: A_t = expE_t * (W^T A_{t-1})
            float p = (lane < TT) ? (__expf(start_t[lane]) * e_sh[lane]) : 0.f;
            float logS = 0.f;
            for (int t = 1; t <= 256; t++) {
                float e_cur = e_sh[t * TT + lane];   // pad covers lane>=TT at t=511 only
                float* pb = (t & 1) ? pb0 : pb1;
                pb[lane] = (lane < TT) ? p : 0.f;
                __syncwarp();
                float s;
                DOT25_SMEM(pb, s);
                p = s * e_cur;
                if ((t & 15) == 0) {
                    float cc = __shfl_sync(full, p, 0);
                    p *= (1.0f / cc);
                    logS += __logf(cc);
                }
            }
            comb[lane] = (lane < TT) ? (__logf(p) + logS) : -INFINITY;
        } else {
            // backward, linear domain: B_{t-1} = W (expE_t ⊙ B_t)
            float p = (lane < TT) ? __expf(end_t[lane]) : 0.f;
            float logS = 0.f;
            for (int t = 511; t >= 257; t--) {
                float e_cur = e_sh[t * TT + lane];
                float q = p * e_cur;
                float* pb = (t & 1) ? pb0 : pb1;
                pb[lane] = (lane < TT) ? q : 0.f;
                __syncwarp();
                DOT25_SMEM(pb, p);
                if ((t & 15) == 0) {
                    float cc = __shfl_sync(full, p, 0);
                    p *= (1.0f / cc);
                    logS += __logf(cc);
                }
            }
            comb[32 + lane] = (lane < TT) ? (__logf(p) + logS) : -INFINITY;
        }
        __syncthreads();

        if (warp == 0) {
            float v = (lane < TT) ? (comb[lane] + comb[32 + lane]) : -INFINITY;
            float M2 = v;
            #pragma unroll
            for (int off = 16; off > 0; off >>= 1)
                M2 = fmaxf(M2, __shfl_xor_sync(full, M2, off));
            float s2 = (lane < TT) ? __expf(v - M2) : 0.f;
            #pragma unroll
            for (int off = 16; off > 0; off >>= 1)
                s2 += __shfl_xor_sync(full, s2, off);

            if (lane == 0) {
                int lab0 = li[base * lstride];
                float score0 = start_t[lab0] + Eb[lab0];
                int last_tag = li[(base + SS - 1) * lstride];
                float numerator = score0 + (nacc[0] + nacc[1]) + end_t[last_tag];
                float logZ = M2 + __logf(s2);
                g_ll[b] = numerator - logZ;
            }
        }
    } else {
        // -------- fallback: serial masked log-domain scan in warp 0 --------
        __syncthreads();
        if (warp == 0) {
            float alpha = (lane < TT) ? (start_t[lane] + Eb[lane]) : -INFINITY;
            float e_next = (lane < TT) ? Eb[1 * TT + lane] : 0.f;
            unsigned char m_next = msh[1];
            for (int t = 1; t < SS; t++) {
                float e_cur = e_next;
                unsigned char m_cur = m_next;
                if (t + 1 < SS) {
                    e_next = (lane < TT) ? Eb[(t + 1) * TT + lane] : 0.f;
                    m_next = msh[t + 1];
                }
                float M = __shfl_sync(full, alpha, 0);
                float p = __expf(alpha - M);
                float s;
                MATVEC25(p, s);
                float nv = e_cur + M + __logf(s);
                if (lane < TT && m_cur) alpha = nv;
            }
            float v = (lane < TT) ? (alpha + end_t[lane]) : -INFINITY;
            float M2 = v;
            #pragma unroll
            for (int off = 16; off > 0; off >>= 1)
                M2 = fmaxf(M2, __shfl_xor_sync(full, M2, off));
            float s2 = (lane < TT) ? __expf(v - M2) : 0.f;
            #pragma unroll
            for (int off = 16; off > 0; off >>= 1)
                s2 += __shfl_xor_sync(full, s2, off);

            if (lane == 0) {
                int lab0 = li[base * lstride];
                float score0 = start_t[lab0] + Eb[lab0];
                int last_idx = (ncnt[0] + ncnt[1]) - 1;
                int last_tag = li[(base + last_idx) * lstride];
                float numerator = score0 + (nacc[0] + nacc[1]) + end_t[last_tag];
                float logZ = M2 + __logf(s2);
                g_ll[b] = numerator - logZ;
            }
        }
    }
}

// ============================================================================
// finalize: out = -mean(ll)
// ============================================================================
__global__ void finalize_kernel(float* __restrict__ out)
{
    __shared__ float sbuf[2];
    const int l = threadIdx.x; // 64 threads
    float v = g_ll[l];
    #pragma unroll
    for (int off = 16; off > 0; off >>= 1)
        v += __shfl_xor_sync(0xffffffffu, v, off);
    if ((l & 31) == 0) sbuf[l >> 5] = v;
    __syncthreads();
    if (l == 0) out[0] = -(sbuf[0] + sbuf[1]) / (float)BB;
}

// ============================================================================
// launch  (crf at index 3 -> profiled)
// ============================================================================
extern "C" void kernel_launch(void* const* d_in, const int* in_sizes, int n_in,
                              void* d_out, int out_size)
{
    const float* X       = (const float*)d_in[0];
    const float* W1      = (const float*)d_in[1];
    const float* b1      = (const float*)d_in[2];
    const float* W2      = (const float*)d_in[3];
    const float* b2      = (const float*)d_in[4];
    const float* start_t = (const float*)d_in[5];
    const float* end_t   = (const float*)d_in[6];
    const float* trans   = (const float*)d_in[7];
    const void*  labels  = d_in[8];
    const void*  mask    = d_in[9];
    float* out = (float*)d_out;

    convert_all_kernel<<<XBLOCKS + WBLOCKS, 256>>>(X, W1);

    cudaFuncSetAttribute(gemm1_fused_kernel,
                         cudaFuncAttributeMaxDynamicSharedMemorySize, SMEM_DYN);
    dim3 g1(HH / 128, MROWS / 128);
    gemm1_fused_kernel<<<g1, 256, SMEM_DYN>>>(b1, W2);

    reduce_E_kernel<<<(MROWS * TT + 255) / 256, 256>>>(b2);

    cudaFuncSetAttribute(crf_kernel,
                         cudaFuncAttributeMaxDynamicSharedMemorySize, CRF_SMEM);
    crf_kernel<<<BB, 64, CRF_SMEM>>>(start_t, end_t, trans, labels, mask);

    finalize_kernel<<<1, 64>>>(out);
}